// round 4
// baseline (speedup 1.0000x reference)
#include <cuda_runtime.h>
#include <math.h>

#define H 128
#define MAXN 100000
#define MAXE 200000
#define NBUCK 21   // levels 1..7 x 3 gate types

// ---------------- static device scratch (allocation-free) ----------------
__device__ float g_scr[MAXE * H];      // per-edge activations (in-place across layers)
__device__ float g_msg[MAXN * H];      // aggregated messages per node
__device__ float g_comb[6 * H];        // hs lookup table per gate type
__device__ float g_wihT[3 * H * 384];  // transposed GRU input weights
__device__ int   g_esorted[MAXE];
__device__ int   g_nsorted[MAXN];
__device__ int   g_ecnt[NBUCK], g_eoff[NBUCK + 1], g_ecur[NBUCK];
__device__ int   g_ncnt[NBUCK], g_noff[NBUCK + 1], g_ncur[NBUCK];

__device__ __forceinline__ int gimap(int g) {
    // gate code 3 -> 0 (AND), 2 -> 1 (NOT), 5 -> 2 (XOR), else -1
    if (g == 3) return 0;
    if (g == 2) return 1;
    if (g == 5) return 2;
    return -1;
}

__device__ __forceinline__ float4 relu4(float4 a) {
    a.x = fmaxf(a.x, 0.f); a.y = fmaxf(a.y, 0.f);
    a.z = fmaxf(a.z, 0.f); a.w = fmaxf(a.w, 0.f);
    return a;
}

__device__ __forceinline__ float sigm(float x) { return 1.f / (1.f + __expf(-x)); }

// ---------------- prep kernels ----------------

// comb[g] = concat(Ws[g], Wt[g]) @ hs_W + hs_b   (only 6 rows!)
__global__ void k_comb(const float* __restrict__ Ws, const float* __restrict__ Wt,
                       const float* __restrict__ hsW, const float* __restrict__ hsb) {
    int g = blockIdx.x, h = threadIdx.x;
    float acc = hsb[h];
#pragma unroll 4
    for (int k = 0; k < H; k++) {
        acc += Ws[g * H + k] * hsW[k * H + h];
        acc += Wt[g * H + k] * hsW[(H + k) * H + h];
    }
    g_comb[g * H + h] = acc;
}

// wihT[gi][k][j] = gru_wih[gi][j][k]  (for coalesced GEMV access)
__global__ void k_transpose(const float* __restrict__ wih) {
    int idx = blockIdx.x * blockDim.x + threadIdx.x;
    if (idx >= 3 * 384 * H) return;
    int k  = idx % H;
    int j  = (idx / H) % 384;
    int gi = idx / (384 * H);
    g_wihT[(gi * H + k) * 384 + j] = wih[(gi * 384 + j) * H + k];
}

// hs gather from table, hf = 0, msg = 0
__global__ void k_init(const int* __restrict__ gate, float* __restrict__ hs,
                       float* __restrict__ hf, int n) {
    int idx = blockIdx.x * blockDim.x + threadIdx.x;
    if (idx >= n * H) return;
    hs[idx] = g_comb[gate[idx >> 7] * H + (idx & 127)];
    hf[idx] = 0.f;
    g_msg[idx] = 0.f;
}

__global__ void k_zero() {
    int t = threadIdx.x;
    if (t < NBUCK) { g_ecnt[t] = 0; g_ncnt[t] = 0; }
}

__global__ void k_count(const int* __restrict__ ei, const int* __restrict__ gate,
                        const int* __restrict__ lvl, int e, int n) {
    int i = blockIdx.x * blockDim.x + threadIdx.x;
    if (i < e) {
        int d = ei[e + i];                   // dst
        int gi = gimap(gate[d]); int lv = lvl[d];
        if (gi >= 0 && lv >= 1) atomicAdd(&g_ecnt[(lv - 1) * 3 + gi], 1);
    }
    if (i < n) {
        int gi = gimap(gate[i]); int lv = lvl[i];
        if (gi >= 0 && lv >= 1) atomicAdd(&g_ncnt[(lv - 1) * 3 + gi], 1);
    }
}

__global__ void k_scan() {
    int se = 0, sn = 0;
    for (int b = 0; b < NBUCK; b++) {
        g_eoff[b] = se; g_ecur[b] = se; se += g_ecnt[b];
        g_noff[b] = sn; g_ncur[b] = sn; sn += g_ncnt[b];
    }
    g_eoff[NBUCK] = se; g_noff[NBUCK] = sn;
}

__global__ void k_scatter(const int* __restrict__ ei, const int* __restrict__ gate,
                          const int* __restrict__ lvl, int e, int n) {
    int i = blockIdx.x * blockDim.x + threadIdx.x;
    if (i < e) {
        int d = ei[e + i];
        int gi = gimap(gate[d]); int lv = lvl[d];
        if (gi >= 0 && lv >= 1) {
            int pos = atomicAdd(&g_ecur[(lv - 1) * 3 + gi], 1);
            g_esorted[pos] = i;
        }
    }
    if (i < n) {
        int gi = gimap(gate[i]); int lv = lvl[i];
        if (gi >= 0 && lv >= 1) {
            int pos = atomicAdd(&g_ncur[(lv - 1) * 3 + gi], 1);
            g_nsorted[pos] = i;
        }
    }
}

// ---------------- per-level compute kernels ----------------
// One warp processes 2 edges so each weight LDG.128 feeds 8 FFMAs.
// blockIdx.y = gate-type -> each SM's L1 sees one (<=128KB) weight set.

__global__ void k_l1(const int* __restrict__ ei,
                     const float* __restrict__ w1, const float* __restrict__ b1,
                     const float* __restrict__ hs, const float* __restrict__ hf,
                     int b0) {
    int gi = blockIdx.y;
    int b = b0 + gi;
    int lo = g_eoff[b], hi = g_eoff[b + 1];
    int lane = threadIdx.x & 31, wl = threadIdx.x >> 5;
    int warp = (blockIdx.x * blockDim.x + threadIdx.x) >> 5;
    int nw = (gridDim.x * blockDim.x) >> 5;
    __shared__ float xs[8][2][256];
    const float* W = w1 + gi * 256 * H;
    float4 bias = *(const float4*)&b1[gi * H + lane * 4];
    for (int p = lo + warp * 2; p < hi; p += nw * 2) {
        bool has2 = (p + 1 < hi);
        int e0 = g_esorted[p];
        int e1 = has2 ? g_esorted[p + 1] : e0;
        int s0 = ei[e0], s1 = ei[e1];
        *(float4*)&xs[wl][0][lane * 4]     = *(const float4*)&hs[s0 * H + lane * 4];
        *(float4*)&xs[wl][0][H + lane * 4] = *(const float4*)&hf[s0 * H + lane * 4];
        *(float4*)&xs[wl][1][lane * 4]     = *(const float4*)&hs[s1 * H + lane * 4];
        *(float4*)&xs[wl][1][H + lane * 4] = *(const float4*)&hf[s1 * H + lane * 4];
        __syncwarp();
        float4 a0 = bias, a1 = bias;
#pragma unroll 4
        for (int k = 0; k < 256; k++) {
            float4 w = *(const float4*)&W[k * H + lane * 4];
            float x0 = xs[wl][0][k], x1 = xs[wl][1][k];
            a0.x += x0 * w.x; a0.y += x0 * w.y; a0.z += x0 * w.z; a0.w += x0 * w.w;
            a1.x += x1 * w.x; a1.y += x1 * w.y; a1.z += x1 * w.z; a1.w += x1 * w.w;
        }
        a0 = relu4(a0); a1 = relu4(a1);
        *(float4*)&g_scr[p * H + lane * 4] = a0;
        if (has2) *(float4*)&g_scr[(p + 1) * H + lane * 4] = a1;
        __syncwarp();
    }
}

__global__ void k_l2(const float* __restrict__ w2, const float* __restrict__ b2, int b0) {
    int gi = blockIdx.y;
    int b = b0 + gi;
    int lo = g_eoff[b], hi = g_eoff[b + 1];
    int lane = threadIdx.x & 31, wl = threadIdx.x >> 5;
    int warp = (blockIdx.x * blockDim.x + threadIdx.x) >> 5;
    int nw = (gridDim.x * blockDim.x) >> 5;
    __shared__ float xs[8][2][128];
    const float* W = w2 + gi * H * H;
    float4 bias = *(const float4*)&b2[gi * H + lane * 4];
    for (int p = lo + warp * 2; p < hi; p += nw * 2) {
        bool has2 = (p + 1 < hi);
        int p1 = has2 ? p + 1 : p;
        *(float4*)&xs[wl][0][lane * 4] = *(const float4*)&g_scr[p * H + lane * 4];
        *(float4*)&xs[wl][1][lane * 4] = *(const float4*)&g_scr[p1 * H + lane * 4];
        __syncwarp();
        float4 a0 = bias, a1 = bias;
#pragma unroll 4
        for (int k = 0; k < 128; k++) {
            float4 w = *(const float4*)&W[k * H + lane * 4];
            float x0 = xs[wl][0][k], x1 = xs[wl][1][k];
            a0.x += x0 * w.x; a0.y += x0 * w.y; a0.z += x0 * w.z; a0.w += x0 * w.w;
            a1.x += x1 * w.x; a1.y += x1 * w.y; a1.z += x1 * w.z; a1.w += x1 * w.w;
        }
        a0 = relu4(a0); a1 = relu4(a1);
        *(float4*)&g_scr[p * H + lane * 4] = a0;
        if (has2) *(float4*)&g_scr[(p + 1) * H + lane * 4] = a1;
        __syncwarp();
    }
}

__global__ void k_l3(const int* __restrict__ ei,
                     const float* __restrict__ w3, const float* __restrict__ b3,
                     int b0, int e) {
    int gi = blockIdx.y;
    int b = b0 + gi;
    int lo = g_eoff[b], hi = g_eoff[b + 1];
    int lane = threadIdx.x & 31, wl = threadIdx.x >> 5;
    int warp = (blockIdx.x * blockDim.x + threadIdx.x) >> 5;
    int nw = (gridDim.x * blockDim.x) >> 5;
    __shared__ float xs[8][2][128];
    const float* W = w3 + gi * H * H;
    float4 bias = *(const float4*)&b3[gi * H + lane * 4];
    for (int p = lo + warp * 2; p < hi; p += nw * 2) {
        bool has2 = (p + 1 < hi);
        int p1 = has2 ? p + 1 : p;
        int e0 = g_esorted[p];
        int e1 = g_esorted[p1];
        *(float4*)&xs[wl][0][lane * 4] = *(const float4*)&g_scr[p * H + lane * 4];
        *(float4*)&xs[wl][1][lane * 4] = *(const float4*)&g_scr[p1 * H + lane * 4];
        __syncwarp();
        float4 a0 = bias, a1 = bias;
#pragma unroll 4
        for (int k = 0; k < 128; k++) {
            float4 w = *(const float4*)&W[k * H + lane * 4];
            float x0 = xs[wl][0][k], x1 = xs[wl][1][k];
            a0.x += x0 * w.x; a0.y += x0 * w.y; a0.z += x0 * w.z; a0.w += x0 * w.w;
            a1.x += x1 * w.x; a1.y += x1 * w.y; a1.z += x1 * w.z; a1.w += x1 * w.w;
        }
        int d0 = ei[e + e0];
        int c = lane * 4;
        atomicAdd(&g_msg[d0 * H + c + 0], a0.x);
        atomicAdd(&g_msg[d0 * H + c + 1], a0.y);
        atomicAdd(&g_msg[d0 * H + c + 2], a0.z);
        atomicAdd(&g_msg[d0 * H + c + 3], a0.w);
        if (has2) {
            int d1 = ei[e + e1];
            atomicAdd(&g_msg[d1 * H + c + 0], a1.x);
            atomicAdd(&g_msg[d1 * H + c + 1], a1.y);
            atomicAdd(&g_msg[d1 * H + c + 2], a1.z);
            atomicAdd(&g_msg[d1 * H + c + 3], a1.w);
        }
        __syncwarp();
    }
}

// GRU with h_old == 0 (each node updated exactly once, hf starts at 0):
//   gin = msg @ wih.T + bih ;  gh = bhh
//   r = sig(i_r + bhh_r), z = sig(i_z + bhh_z), nst = tanh(i_n + r*bhh_n)
//   hf = (1 - z) * nst
__global__ void k_gru(const float* __restrict__ bih, const float* __restrict__ bhh,
                      float* __restrict__ hf, int b0) {
    int gi = blockIdx.y;
    int b = b0 + gi;
    int lo = g_noff[b], hi = g_noff[b + 1];
    int lane = threadIdx.x & 31, wl = threadIdx.x >> 5;
    int warp = (blockIdx.x * blockDim.x + threadIdx.x) >> 5;
    int nw = (gridDim.x * blockDim.x) >> 5;
    __shared__ float ms[8][128];
    const float* WT = g_wihT + gi * H * 384;
    const float* BI = bih + gi * 384;
    const float* BH = bhh + gi * 384;
    int c = lane * 4;
    float4 bR = *(const float4*)&BI[c];
    float4 bZ = *(const float4*)&BI[128 + c];
    float4 bN = *(const float4*)&BI[256 + c];
    float4 hR = *(const float4*)&BH[c];
    float4 hZ = *(const float4*)&BH[128 + c];
    float4 hN = *(const float4*)&BH[256 + c];
    for (int p = lo + warp; p < hi; p += nw) {
        int v = g_nsorted[p];
        *(float4*)&ms[wl][c] = *(const float4*)&g_msg[v * H + c];
        __syncwarp();
        float4 aR = bR, aZ = bZ, aN = bN;
#pragma unroll 2
        for (int k = 0; k < 128; k++) {
            float mk = ms[wl][k];
            float4 wr = *(const float4*)&WT[k * 384 + c];
            float4 wz = *(const float4*)&WT[k * 384 + 128 + c];
            float4 wn = *(const float4*)&WT[k * 384 + 256 + c];
            aR.x += mk * wr.x; aR.y += mk * wr.y; aR.z += mk * wr.z; aR.w += mk * wr.w;
            aZ.x += mk * wz.x; aZ.y += mk * wz.y; aZ.z += mk * wz.z; aZ.w += mk * wz.w;
            aN.x += mk * wn.x; aN.y += mk * wn.y; aN.z += mk * wn.z; aN.w += mk * wn.w;
        }
        float4 out;
        {
            float r, z, nst;
            r = sigm(aR.x + hR.x); z = sigm(aZ.x + hZ.x);
            nst = tanhf(aN.x + r * hN.x); out.x = (1.f - z) * nst;
            r = sigm(aR.y + hR.y); z = sigm(aZ.y + hZ.y);
            nst = tanhf(aN.y + r * hN.y); out.y = (1.f - z) * nst;
            r = sigm(aR.z + hR.z); z = sigm(aZ.z + hZ.z);
            nst = tanhf(aN.z + r * hN.z); out.z = (1.f - z) * nst;
            r = sigm(aR.w + hR.w); z = sigm(aZ.w + hZ.w);
            nst = tanhf(aN.w + r * hN.w); out.w = (1.f - z) * nst;
        }
        *(float4*)&hf[v * H + c] = out;
        __syncwarp();
    }
}

// ---------------- launch ----------------
extern "C" void kernel_launch(void* const* d_in, const int* in_sizes, int n_in,
                              void* d_out, int out_size) {
    const int*   gate = (const int*)d_in[0];
    const int*   lvl  = (const int*)d_in[1];
    const int*   ei   = (const int*)d_in[2];
    const float* Ws   = (const float*)d_in[3];
    const float* Wt   = (const float*)d_in[4];
    const float* hsW  = (const float*)d_in[5];
    const float* hsb  = (const float*)d_in[6];
    const float* w1   = (const float*)d_in[7];
    const float* b1   = (const float*)d_in[8];
    const float* w2   = (const float*)d_in[9];
    const float* b2   = (const float*)d_in[10];
    const float* w3   = (const float*)d_in[11];
    const float* b3   = (const float*)d_in[12];
    const float* wih  = (const float*)d_in[13];
    // d_in[14] = gru_whh: provably unused (h_old == 0 for every updated node)
    const float* bih  = (const float*)d_in[15];
    const float* bhh  = (const float*)d_in[16];

    int n = in_sizes[0];
    int e = in_sizes[2] / 2;

    float* hs = (float*)d_out;            // output: [hs (N*H) | hf (N*H)]
    float* hf = hs + (size_t)n * H;

    k_comb<<<6, H>>>(Ws, Wt, hsW, hsb);
    k_transpose<<<(3 * 384 * H + 255) / 256, 256>>>(wih);
    k_init<<<(n * H + 255) / 256, 256>>>(gate, hs, hf, n);
    k_zero<<<1, 32>>>();
    k_count<<<(e + 255) / 256, 256>>>(ei, gate, lvl, e, n);
    k_scan<<<1, 1>>>();
    k_scatter<<<(e + 255) / 256, 256>>>(ei, gate, lvl, e, n);

    for (int lv = 1; lv < 8; lv++) {
        int b0 = (lv - 1) * 3;
        k_l1<<<dim3(48, 3), 256>>>(ei, w1, b1, hs, hf, b0);
        k_l2<<<dim3(48, 3), 256>>>(w2, b2, b0);
        k_l3<<<dim3(48, 3), 256>>>(ei, w3, b3, b0, e);
        k_gru<<<dim3(32, 3), 256>>>(bih, bhh, hf, b0);
    }
}

// round 6
// speedup vs baseline: 1.9074x; 1.9074x over previous
#include <cuda_runtime.h>
#include <math.h>

#define H 128
#define MAXN 100000
#define MAXE 200000
#define NBUCK 21   // levels 1..7 x 3 gate types

// ---------------- static device scratch (allocation-free) ----------------
__device__ float g_msg[MAXN * H];      // aggregated messages per node
__device__ float g_comb[6 * H];        // hs lookup table per gate type
__device__ float g_T[3 * 6 * H];       // layer-1 partial: b1 + comb[g] @ W1_top
__device__ float g_wihT[3 * H * 384];  // transposed GRU input weights
__device__ int   g_esorted[MAXE];
__device__ int   g_nsorted[MAXN];
__device__ int   g_ecnt[NBUCK], g_eoff[NBUCK + 1], g_ecur[NBUCK];
__device__ int   g_ncnt[NBUCK], g_noff[NBUCK + 1], g_ncur[NBUCK];

__device__ __forceinline__ int gimap(int g) {
    if (g == 3) return 0;   // AND
    if (g == 2) return 1;   // NOT
    if (g == 5) return 2;   // XOR
    return -1;
}

__device__ __forceinline__ float4 relu4(float4 a) {
    a.x = fmaxf(a.x, 0.f); a.y = fmaxf(a.y, 0.f);
    a.z = fmaxf(a.z, 0.f); a.w = fmaxf(a.w, 0.f);
    return a;
}

__device__ __forceinline__ float sigm(float x) { return 1.f / (1.f + __expf(-x)); }

__device__ __forceinline__ void fma4(float4& acc, float s, float4 v) {
    acc.x += s * v.x; acc.y += s * v.y; acc.z += s * v.z; acc.w += s * v.w;
}

// ---------------- prep kernels ----------------

// comb[g] = concat(Ws[g], Wt[g]) @ hs_W + hs_b   (only 6 rows!)
__global__ void k_comb(const float* __restrict__ Ws, const float* __restrict__ Wt,
                       const float* __restrict__ hsW, const float* __restrict__ hsb) {
    int g = blockIdx.x, h = threadIdx.x;
    float acc = hsb[h];
#pragma unroll 4
    for (int k = 0; k < H; k++) {
        acc += Ws[g * H + k] * hsW[k * H + h];
        acc += Wt[g * H + k] * hsW[(H + k) * H + h];
    }
    g_comb[g * H + h] = acc;
}

// T[gi][g] = b1[gi] + comb[g] @ W1[gi][0:128,:]   (hs-half of layer 1 folded)
__global__ void k_table(const float* __restrict__ w1, const float* __restrict__ b1) {
    int g = blockIdx.x, gi = blockIdx.y, h = threadIdx.x;
    float acc = b1[gi * H + h];
    const float* W = w1 + gi * 256 * H;     // top half: rows 0..127
#pragma unroll 4
    for (int k = 0; k < H; k++)
        acc += g_comb[g * H + k] * W[k * H + h];
    g_T[(gi * 6 + g) * H + h] = acc;
}

// wihT[gi][k][j] = gru_wih[gi][j][k]
__global__ void k_transpose(const float* __restrict__ wih) {
    int idx = blockIdx.x * blockDim.x + threadIdx.x;
    if (idx >= 3 * 384 * H) return;
    int k  = idx % H;
    int j  = (idx / H) % 384;
    int gi = idx / (384 * H);
    g_wihT[(gi * H + k) * 384 + j] = wih[(gi * 384 + j) * H + k];
}

// hs gather from table, hf = 0, msg = 0
__global__ void k_init(const int* __restrict__ gate, float* __restrict__ hs,
                       float* __restrict__ hf, int n) {
    int idx = blockIdx.x * blockDim.x + threadIdx.x;
    if (idx >= n * H) return;
    hs[idx] = g_comb[gate[idx >> 7] * H + (idx & 127)];
    hf[idx] = 0.f;
    g_msg[idx] = 0.f;
}

__global__ void k_zero() {
    int t = threadIdx.x;
    if (t < NBUCK) { g_ecnt[t] = 0; g_ncnt[t] = 0; }
}

__global__ void k_count(const int* __restrict__ ei, const int* __restrict__ gate,
                        const int* __restrict__ lvl, int e, int n) {
    int i = blockIdx.x * blockDim.x + threadIdx.x;
    if (i < e) {
        int d = ei[e + i];
        int gi = gimap(gate[d]); int lv = lvl[d];
        if (gi >= 0 && lv >= 1) atomicAdd(&g_ecnt[(lv - 1) * 3 + gi], 1);
    }
    if (i < n) {
        int gi = gimap(gate[i]); int lv = lvl[i];
        if (gi >= 0 && lv >= 1) atomicAdd(&g_ncnt[(lv - 1) * 3 + gi], 1);
    }
}

__global__ void k_scan() {
    int se = 0, sn = 0;
    for (int b = 0; b < NBUCK; b++) {
        g_eoff[b] = se; g_ecur[b] = se; se += g_ecnt[b];
        g_noff[b] = sn; g_ncur[b] = sn; sn += g_ncnt[b];
    }
    g_eoff[NBUCK] = se; g_noff[NBUCK] = sn;
}

__global__ void k_scatter(const int* __restrict__ ei, const int* __restrict__ gate,
                          const int* __restrict__ lvl, int e, int n) {
    int i = blockIdx.x * blockDim.x + threadIdx.x;
    if (i < e) {
        int d = ei[e + i];
        int gi = gimap(gate[d]); int lv = lvl[d];
        if (gi >= 0 && lv >= 1) {
            int pos = atomicAdd(&g_ecur[(lv - 1) * 3 + gi], 1);
            g_esorted[pos] = i;
        }
    }
    if (i < n) {
        int gi = gimap(gate[i]); int lv = lvl[i];
        if (gi >= 0 && lv >= 1) {
            int pos = atomicAdd(&g_ncur[(lv - 1) * 3 + gi], 1);
            g_nsorted[pos] = i;
        }
    }
}

// ---------------- fused per-level edge kernel ----------------
// One warp processes 4 edges through all 3 MLP layers + atomic scatter.
// Layer-1 hs-half replaced by table lookup (K halved to 128, over hf only).
// Each weight LDG.128 feeds 16 FFMAs.

__global__ void __launch_bounds__(256) k_level(
        const int* __restrict__ ei, const int* __restrict__ gate,
        const float* __restrict__ w1,
        const float* __restrict__ w2, const float* __restrict__ b2,
        const float* __restrict__ w3, const float* __restrict__ b3,
        const float* __restrict__ hf, int b0, int e) {
    int gi = blockIdx.y;
    int b  = b0 + gi;
    int lo = g_eoff[b], hi = g_eoff[b + 1];
    int lane = threadIdx.x & 31, wl = threadIdx.x >> 5;
    int warp = (blockIdx.x * blockDim.x + threadIdx.x) >> 5;
    int nw   = (gridDim.x * blockDim.x) >> 5;
    __shared__ float xs[8][4][128];    // 16KB: per-warp 4-edge activation buffer
    const float* W1b = w1 + gi * 256 * H + 128 * H;   // bottom half (hf part)
    const float* W2  = w2 + gi * H * H;
    const float* W3  = w3 + gi * H * H;
    int c = lane * 4;
    float4 bias2 = *(const float4*)&b2[gi * H + c];
    float4 bias3 = *(const float4*)&b3[gi * H + c];

    for (int p = lo + warp * 4; p < hi; p += nw * 4) {
        int eid[4]; bool m[4];
        float4 a0, a1, a2, a3;
#pragma unroll
        for (int q = 0; q < 4; q++) {
            int idx = p + q; m[q] = idx < hi;
            if (!m[q]) idx = hi - 1;
            eid[q] = g_esorted[idx];
        }
        // stage hf[src] and init accum from table (hs-half folded in)
        {
            int s0 = ei[eid[0]], s1 = ei[eid[1]], s2 = ei[eid[2]], s3 = ei[eid[3]];
            *(float4*)&xs[wl][0][c] = *(const float4*)&hf[s0 * H + c];
            *(float4*)&xs[wl][1][c] = *(const float4*)&hf[s1 * H + c];
            *(float4*)&xs[wl][2][c] = *(const float4*)&hf[s2 * H + c];
            *(float4*)&xs[wl][3][c] = *(const float4*)&hf[s3 * H + c];
            a0 = *(const float4*)&g_T[(gi * 6 + gate[s0]) * H + c];
            a1 = *(const float4*)&g_T[(gi * 6 + gate[s1]) * H + c];
            a2 = *(const float4*)&g_T[(gi * 6 + gate[s2]) * H + c];
            a3 = *(const float4*)&g_T[(gi * 6 + gate[s3]) * H + c];
        }
        __syncwarp();
        // layer 1 (hf-half, K=128)
#pragma unroll 4
        for (int k = 0; k < 128; k++) {
            float4 w = *(const float4*)&W1b[k * H + c];
            fma4(a0, xs[wl][0][k], w); fma4(a1, xs[wl][1][k], w);
            fma4(a2, xs[wl][2][k], w); fma4(a3, xs[wl][3][k], w);
        }
        a0 = relu4(a0); a1 = relu4(a1); a2 = relu4(a2); a3 = relu4(a3);
        __syncwarp();
        *(float4*)&xs[wl][0][c] = a0; *(float4*)&xs[wl][1][c] = a1;
        *(float4*)&xs[wl][2][c] = a2; *(float4*)&xs[wl][3][c] = a3;
        __syncwarp();
        // layer 2
        a0 = bias2; a1 = bias2; a2 = bias2; a3 = bias2;
#pragma unroll 4
        for (int k = 0; k < 128; k++) {
            float4 w = *(const float4*)&W2[k * H + c];
            fma4(a0, xs[wl][0][k], w); fma4(a1, xs[wl][1][k], w);
            fma4(a2, xs[wl][2][k], w); fma4(a3, xs[wl][3][k], w);
        }
        a0 = relu4(a0); a1 = relu4(a1); a2 = relu4(a2); a3 = relu4(a3);
        __syncwarp();
        *(float4*)&xs[wl][0][c] = a0; *(float4*)&xs[wl][1][c] = a1;
        *(float4*)&xs[wl][2][c] = a2; *(float4*)&xs[wl][3][c] = a3;
        __syncwarp();
        // layer 3
        a0 = bias3; a1 = bias3; a2 = bias3; a3 = bias3;
#pragma unroll 4
        for (int k = 0; k < 128; k++) {
            float4 w = *(const float4*)&W3[k * H + c];
            fma4(a0, xs[wl][0][k], w); fma4(a1, xs[wl][1][k], w);
            fma4(a2, xs[wl][2][k], w); fma4(a3, xs[wl][3][k], w);
        }
        // scatter-add to dst
#pragma unroll
        for (int q = 0; q < 4; q++) {
            if (!m[q]) break;
            float4 a = (q == 0) ? a0 : (q == 1) ? a1 : (q == 2) ? a2 : a3;
            int d = ei[e + eid[q]];
            atomicAdd(&g_msg[d * H + c + 0], a.x);
            atomicAdd(&g_msg[d * H + c + 1], a.y);
            atomicAdd(&g_msg[d * H + c + 2], a.z);
            atomicAdd(&g_msg[d * H + c + 3], a.w);
        }
        __syncwarp();
    }
}

// GRU with h_old == 0: hf = (1 - z) * tanh(i_n + r * bhh_n), 2 nodes per warp.
__global__ void __launch_bounds__(256) k_gru(
        const float* __restrict__ bih, const float* __restrict__ bhh,
        float* __restrict__ hf, int b0) {
    int gi = blockIdx.y;
    int b  = b0 + gi;
    int lo = g_noff[b], hi = g_noff[b + 1];
    int lane = threadIdx.x & 31, wl = threadIdx.x >> 5;
    int warp = (blockIdx.x * blockDim.x + threadIdx.x) >> 5;
    int nw   = (gridDim.x * blockDim.x) >> 5;
    __shared__ float ms[8][2][128];
    const float* WT = g_wihT + gi * H * 384;
    const float* BI = bih + gi * 384;
    const float* BH = bhh + gi * 384;
    int c = lane * 4;
    float4 bR = *(const float4*)&BI[c];
    float4 bZ = *(const float4*)&BI[128 + c];
    float4 bN = *(const float4*)&BI[256 + c];
    float4 hR = *(const float4*)&BH[c];
    float4 hZ = *(const float4*)&BH[128 + c];
    float4 hN = *(const float4*)&BH[256 + c];
    for (int p = lo + warp * 2; p < hi; p += nw * 2) {
        bool m1 = (p + 1 < hi);
        int v0 = g_nsorted[p];
        int v1 = g_nsorted[m1 ? p + 1 : p];
        *(float4*)&ms[wl][0][c] = *(const float4*)&g_msg[v0 * H + c];
        *(float4*)&ms[wl][1][c] = *(const float4*)&g_msg[v1 * H + c];
        __syncwarp();
        float4 aR0 = bR, aZ0 = bZ, aN0 = bN;
        float4 aR1 = bR, aZ1 = bZ, aN1 = bN;
#pragma unroll 2
        for (int k = 0; k < 128; k++) {
            float m0 = ms[wl][0][k], m1v = ms[wl][1][k];
            float4 wr = *(const float4*)&WT[k * 384 + c];
            float4 wz = *(const float4*)&WT[k * 384 + 128 + c];
            float4 wn = *(const float4*)&WT[k * 384 + 256 + c];
            fma4(aR0, m0, wr); fma4(aZ0, m0, wz); fma4(aN0, m0, wn);
            fma4(aR1, m1v, wr); fma4(aZ1, m1v, wz); fma4(aN1, m1v, wn);
        }
        float4 o0, o1;
        {
            float r, z;
            r = sigm(aR0.x + hR.x); z = sigm(aZ0.x + hZ.x); o0.x = (1.f - z) * tanhf(aN0.x + r * hN.x);
            r = sigm(aR0.y + hR.y); z = sigm(aZ0.y + hZ.y); o0.y = (1.f - z) * tanhf(aN0.y + r * hN.y);
            r = sigm(aR0.z + hR.z); z = sigm(aZ0.z + hZ.z); o0.z = (1.f - z) * tanhf(aN0.z + r * hN.z);
            r = sigm(aR0.w + hR.w); z = sigm(aZ0.w + hZ.w); o0.w = (1.f - z) * tanhf(aN0.w + r * hN.w);
            r = sigm(aR1.x + hR.x); z = sigm(aZ1.x + hZ.x); o1.x = (1.f - z) * tanhf(aN1.x + r * hN.x);
            r = sigm(aR1.y + hR.y); z = sigm(aZ1.y + hZ.y); o1.y = (1.f - z) * tanhf(aN1.y + r * hN.y);
            r = sigm(aR1.z + hR.z); z = sigm(aZ1.z + hZ.z); o1.z = (1.f - z) * tanhf(aN1.z + r * hN.z);
            r = sigm(aR1.w + hR.w); z = sigm(aZ1.w + hZ.w); o1.w = (1.f - z) * tanhf(aN1.w + r * hN.w);
        }
        *(float4*)&hf[v0 * H + c] = o0;
        if (m1) *(float4*)&hf[v1 * H + c] = o1;
        __syncwarp();
    }
}

// ---------------- launch ----------------
extern "C" void kernel_launch(void* const* d_in, const int* in_sizes, int n_in,
                              void* d_out, int out_size) {
    const int*   gate = (const int*)d_in[0];
    const int*   lvl  = (const int*)d_in[1];
    const int*   ei   = (const int*)d_in[2];
    const float* Ws   = (const float*)d_in[3];
    const float* Wt   = (const float*)d_in[4];
    const float* hsW  = (const float*)d_in[5];
    const float* hsb  = (const float*)d_in[6];
    const float* w1   = (const float*)d_in[7];
    const float* b1   = (const float*)d_in[8];
    const float* w2   = (const float*)d_in[9];
    const float* b2   = (const float*)d_in[10];
    const float* w3   = (const float*)d_in[11];
    const float* b3   = (const float*)d_in[12];
    const float* wih  = (const float*)d_in[13];
    // d_in[14] = gru_whh: provably unused (h_old == 0 for every updated node)
    const float* bih  = (const float*)d_in[15];
    const float* bhh  = (const float*)d_in[16];

    int n = in_sizes[0];
    int e = in_sizes[2] / 2;

    float* hs = (float*)d_out;            // output: [hs (N*H) | hf (N*H)]
    float* hf = hs + (size_t)n * H;

    k_comb<<<6, H>>>(Ws, Wt, hsW, hsb);
    k_table<<<dim3(6, 3), H>>>(w1, b1);
    k_transpose<<<(3 * 384 * H + 255) / 256, 256>>>(wih);
    k_init<<<(n * H + 255) / 256, 256>>>(gate, hs, hf, n);
    k_zero<<<1, 32>>>();
    k_count<<<(e + 255) / 256, 256>>>(ei, gate, lvl, e, n);
    k_scan<<<1, 1>>>();
    k_scatter<<<(e + 255) / 256, 256>>>(ei, gate, lvl, e, n);

    for (int lv = 1; lv < 8; lv++) {
        int b0 = (lv - 1) * 3;
        k_level<<<dim3(132, 3), 256>>>(ei, gate, w1, w2, b2, w3, b3, hf, b0, e);
        k_gru<<<dim3(74, 3), 256>>>(bih, bhh, hf, b0);
    }
}

// round 8
// speedup vs baseline: 4.6283x; 2.4265x over previous
#include <cuda_runtime.h>
#include <math.h>

#define H 128
#define MAXN 100000
#define MAXE 200000
#define NBUCK 21   // levels 1..7 x 3 gate types

// ---------------- static device scratch (allocation-free) ----------------
__device__ float g_msg[MAXN * H];      // aggregated messages per node
__device__ float g_comb[6 * H];        // hs lookup table per gate type
__device__ float g_T[3 * 6 * H];       // layer-1 partial: b1 + comb[g] @ W1_top
__device__ float g_wihT[3 * H * 384];  // transposed GRU input weights
__device__ int   g_esorted[MAXE];
__device__ int   g_nsorted[MAXN];
__device__ int   g_ecnt[NBUCK], g_eoff[NBUCK + 1], g_ecur[NBUCK];
__device__ int   g_ncnt[NBUCK], g_noff[NBUCK + 1], g_ncur[NBUCK];

__device__ __forceinline__ int gimap(int g) {
    if (g == 3) return 0;   // AND
    if (g == 2) return 1;   // NOT
    if (g == 5) return 2;   // XOR
    return -1;
}

__device__ __forceinline__ float4 relu4(float4 a) {
    a.x = fmaxf(a.x, 0.f); a.y = fmaxf(a.y, 0.f);
    a.z = fmaxf(a.z, 0.f); a.w = fmaxf(a.w, 0.f);
    return a;
}

__device__ __forceinline__ float sigm(float x) { return 1.f / (1.f + __expf(-x)); }

__device__ __forceinline__ void fma4(float4& acc, float s, float4 v) {
    acc.x += s * v.x; acc.y += s * v.y; acc.z += s * v.z; acc.w += s * v.w;
}

// ---------------- prep kernels ----------------

// comb[g] = concat(Ws[g], Wt[g]) @ hs_W + hs_b   (only 6 rows!)
__global__ void k_comb(const float* __restrict__ Ws, const float* __restrict__ Wt,
                       const float* __restrict__ hsW, const float* __restrict__ hsb) {
    int g = blockIdx.x, h = threadIdx.x;
    float acc = hsb[h];
#pragma unroll 4
    for (int k = 0; k < H; k++) {
        acc += Ws[g * H + k] * hsW[k * H + h];
        acc += Wt[g * H + k] * hsW[(H + k) * H + h];
    }
    g_comb[g * H + h] = acc;
}

// T[gi][g] = b1[gi] + comb[g] @ W1[gi][0:128,:]   (hs-half of layer 1 folded)
__global__ void k_table(const float* __restrict__ w1, const float* __restrict__ b1) {
    int g = blockIdx.x, gi = blockIdx.y, h = threadIdx.x;
    float acc = b1[gi * H + h];
    const float* W = w1 + gi * 256 * H;     // top half: rows 0..127
#pragma unroll 4
    for (int k = 0; k < H; k++)
        acc += g_comb[g * H + k] * W[k * H + h];
    g_T[(gi * 6 + g) * H + h] = acc;
}

// wihT[gi][k][j] = gru_wih[gi][j][k]
__global__ void k_transpose(const float* __restrict__ wih) {
    int idx = blockIdx.x * blockDim.x + threadIdx.x;
    if (idx >= 3 * 384 * H) return;
    int k  = idx % H;
    int j  = (idx / H) % 384;
    int gi = idx / (384 * H);
    g_wihT[(gi * H + k) * 384 + j] = wih[(gi * 384 + j) * H + k];
}

// hs gather from table (float4), hf = 0, msg = 0
__global__ void k_init(const int* __restrict__ gate, float* __restrict__ hs,
                       float* __restrict__ hf, int n) {
    int idx = blockIdx.x * blockDim.x + threadIdx.x;   // over n*32 float4s
    if (idx >= n * 32) return;
    int node = idx >> 5, c4 = idx & 31;
    float4 v = *(const float4*)&g_comb[gate[node] * H + c4 * 4];
    ((float4*)hs)[idx] = v;
    float4 z = make_float4(0.f, 0.f, 0.f, 0.f);
    ((float4*)hf)[idx] = z;
    ((float4*)g_msg)[idx] = z;
}

__global__ void k_zero() {
    int t = threadIdx.x;
    if (t < NBUCK) { g_ecnt[t] = 0; g_ncnt[t] = 0; }
}

__global__ void k_count(const int* __restrict__ ei, const int* __restrict__ gate,
                        const int* __restrict__ lvl, int e, int n) {
    int i = blockIdx.x * blockDim.x + threadIdx.x;
    if (i < e) {
        int d = ei[e + i];
        int gi = gimap(gate[d]); int lv = lvl[d];
        if (gi >= 0 && lv >= 1) atomicAdd(&g_ecnt[(lv - 1) * 3 + gi], 1);
    }
    if (i < n) {
        int gi = gimap(gate[i]); int lv = lvl[i];
        if (gi >= 0 && lv >= 1) atomicAdd(&g_ncnt[(lv - 1) * 3 + gi], 1);
    }
}

__global__ void k_scan() {
    int se = 0, sn = 0;
    for (int b = 0; b < NBUCK; b++) {
        g_eoff[b] = se; g_ecur[b] = se; se += g_ecnt[b];
        g_noff[b] = sn; g_ncur[b] = sn; sn += g_ncnt[b];
    }
    g_eoff[NBUCK] = se; g_noff[NBUCK] = sn;
}

__global__ void k_scatter(const int* __restrict__ ei, const int* __restrict__ gate,
                          const int* __restrict__ lvl, int e, int n) {
    int i = blockIdx.x * blockDim.x + threadIdx.x;
    if (i < e) {
        int d = ei[e + i];
        int gi = gimap(gate[d]); int lv = lvl[d];
        if (gi >= 0 && lv >= 1) {
            int pos = atomicAdd(&g_ecur[(lv - 1) * 3 + gi], 1);
            g_esorted[pos] = i;
        }
    }
    if (i < n) {
        int gi = gimap(gate[i]); int lv = lvl[i];
        if (gi >= 0 && lv >= 1) {
            int pos = atomicAdd(&g_ncur[(lv - 1) * 3 + gi], 1);
            g_nsorted[pos] = i;
        }
    }
}

// ---------------- fused per-level edge kernel ----------------
// All three weight matrices live in 216KB dynamic smem (1 block/SM).
// One warp pushes 4 edges through all 3 MLP layers, then atomic scatter.

#define LVL_SMEM_FLOATS (3 * 128 * 128 + 6 * 128 + 8 * 4 * 128)

__global__ void __launch_bounds__(256) k_level(
        const int* __restrict__ ei, const int* __restrict__ gate,
        const float* __restrict__ w1,
        const float* __restrict__ w2, const float* __restrict__ b2,
        const float* __restrict__ w3, const float* __restrict__ b3,
        const float* __restrict__ hf, int b0, int e) {
    extern __shared__ float sm[];
    float* sW1 = sm;                   // 16384
    float* sW2 = sm + 16384;           // 16384
    float* sW3 = sm + 32768;           // 16384
    float* sT  = sm + 49152;           // 768
    float* sX  = sm + 49920;           // 8 warps * 4 edges * 128

    int gi = blockIdx.y;
    int b  = b0 + gi;
    int lo = g_eoff[b], hi = g_eoff[b + 1];
    int tid = threadIdx.x;
    int lane = tid & 31, wl = tid >> 5;

    // stage weights + table into smem (float4, fully coalesced)
    {
        const float4* s1 = (const float4*)(w1 + gi * 256 * H + 128 * H);
        const float4* s2 = (const float4*)(w2 + gi * H * H);
        const float4* s3 = (const float4*)(w3 + gi * H * H);
        float4* d1 = (float4*)sW1; float4* d2 = (float4*)sW2; float4* d3 = (float4*)sW3;
#pragma unroll
        for (int i = tid; i < 4096; i += 256) {
            d1[i] = s1[i]; d2[i] = s2[i]; d3[i] = s3[i];
        }
        const float4* st = (const float4*)(g_T + gi * 6 * H);
        float4* dt = (float4*)sT;
        if (tid < 192) dt[tid] = st[tid];
    }
    __syncthreads();

    int warp = blockIdx.x * 8 + wl;
    int nw   = gridDim.x * 8;
    int c = lane * 4;
    float4 bias2 = *(const float4*)&b2[gi * H + c];
    float4 bias3 = *(const float4*)&b3[gi * H + c];
    float* xw = sX + wl * 4 * 128;

    for (int p = lo + warp * 4; p < hi; p += nw * 4) {
        int eid[4]; bool m[4];
        float4 a0, a1, a2, a3;
#pragma unroll
        for (int q = 0; q < 4; q++) {
            int idx = p + q; m[q] = idx < hi;
            if (!m[q]) idx = hi - 1;
            eid[q] = g_esorted[idx];
        }
        {
            int s0 = ei[eid[0]], s1 = ei[eid[1]], s2 = ei[eid[2]], s3 = ei[eid[3]];
            *(float4*)&xw[0 * 128 + c] = *(const float4*)&hf[s0 * H + c];
            *(float4*)&xw[1 * 128 + c] = *(const float4*)&hf[s1 * H + c];
            *(float4*)&xw[2 * 128 + c] = *(const float4*)&hf[s2 * H + c];
            *(float4*)&xw[3 * 128 + c] = *(const float4*)&hf[s3 * H + c];
            a0 = *(const float4*)&sT[gate[s0] * H + c];
            a1 = *(const float4*)&sT[gate[s1] * H + c];
            a2 = *(const float4*)&sT[gate[s2] * H + c];
            a3 = *(const float4*)&sT[gate[s3] * H + c];
        }
        __syncwarp();
        // layer 1 (hf-half only; hs-half folded into sT)
#pragma unroll 4
        for (int k = 0; k < 128; k++) {
            float4 w = *(const float4*)&sW1[k * H + c];
            fma4(a0, xw[0 * 128 + k], w); fma4(a1, xw[1 * 128 + k], w);
            fma4(a2, xw[2 * 128 + k], w); fma4(a3, xw[3 * 128 + k], w);
        }
        a0 = relu4(a0); a1 = relu4(a1); a2 = relu4(a2); a3 = relu4(a3);
        __syncwarp();
        *(float4*)&xw[0 * 128 + c] = a0; *(float4*)&xw[1 * 128 + c] = a1;
        *(float4*)&xw[2 * 128 + c] = a2; *(float4*)&xw[3 * 128 + c] = a3;
        __syncwarp();
        // layer 2
        a0 = bias2; a1 = bias2; a2 = bias2; a3 = bias2;
#pragma unroll 4
        for (int k = 0; k < 128; k++) {
            float4 w = *(const float4*)&sW2[k * H + c];
            fma4(a0, xw[0 * 128 + k], w); fma4(a1, xw[1 * 128 + k], w);
            fma4(a2, xw[2 * 128 + k], w); fma4(a3, xw[3 * 128 + k], w);
        }
        a0 = relu4(a0); a1 = relu4(a1); a2 = relu4(a2); a3 = relu4(a3);
        __syncwarp();
        *(float4*)&xw[0 * 128 + c] = a0; *(float4*)&xw[1 * 128 + c] = a1;
        *(float4*)&xw[2 * 128 + c] = a2; *(float4*)&xw[3 * 128 + c] = a3;
        __syncwarp();
        // layer 3
        a0 = bias3; a1 = bias3; a2 = bias3; a3 = bias3;
#pragma unroll 4
        for (int k = 0; k < 128; k++) {
            float4 w = *(const float4*)&sW3[k * H + c];
            fma4(a0, xw[0 * 128 + k], w); fma4(a1, xw[1 * 128 + k], w);
            fma4(a2, xw[2 * 128 + k], w); fma4(a3, xw[3 * 128 + k], w);
        }
        // scatter-add to dst
#pragma unroll
        for (int q = 0; q < 4; q++) {
            if (!m[q]) break;
            float4 a = (q == 0) ? a0 : (q == 1) ? a1 : (q == 2) ? a2 : a3;
            int d = ei[e + eid[q]];
            atomicAdd(&g_msg[d * H + c + 0], a.x);
            atomicAdd(&g_msg[d * H + c + 1], a.y);
            atomicAdd(&g_msg[d * H + c + 2], a.z);
            atomicAdd(&g_msg[d * H + c + 3], a.w);
        }
        __syncwarp();
    }
}

// ---------------- GRU kernel (weights in 208KB smem) ----------------
// h_old == 0: hf = (1 - z) * tanh(i_n + r * bhh_n). 4 nodes per warp.

#define GRU_SMEM_FLOATS (128 * 384 + 8 * 4 * 128)

__global__ void __launch_bounds__(256) k_gru(
        const float* __restrict__ bih, const float* __restrict__ bhh,
        float* __restrict__ hf, int b0) {
    extern __shared__ float sm[];
    float* sWT = sm;                   // 49152 floats
    float* sM  = sm + 49152;           // 8 warps * 4 nodes * 128

    int gi = blockIdx.y;
    int b  = b0 + gi;
    int lo = g_noff[b], hi = g_noff[b + 1];
    int tid = threadIdx.x;
    int lane = tid & 31, wl = tid >> 5;

    {
        const float4* src = (const float4*)(g_wihT + gi * H * 384);
        float4* dst = (float4*)sWT;
#pragma unroll
        for (int i = tid; i < 12288; i += 256) dst[i] = src[i];
    }
    __syncthreads();

    int warp = blockIdx.x * 8 + wl;
    int nw   = gridDim.x * 8;
    int c = lane * 4;
    const float* BI = bih + gi * 384;
    const float* BH = bhh + gi * 384;
    // fold constant bhh_r / bhh_z into the accum init
    float4 cR, cZ, bN, hN;
    {
        float4 bR = *(const float4*)&BI[c];
        float4 bZ = *(const float4*)&BI[128 + c];
        bN = *(const float4*)&BI[256 + c];
        float4 hR = *(const float4*)&BH[c];
        float4 hZ = *(const float4*)&BH[128 + c];
        hN = *(const float4*)&BH[256 + c];
        cR = make_float4(bR.x + hR.x, bR.y + hR.y, bR.z + hR.z, bR.w + hR.w);
        cZ = make_float4(bZ.x + hZ.x, bZ.y + hZ.y, bZ.z + hZ.z, bZ.w + hZ.w);
    }
    float* mw = sM + wl * 4 * 128;

    for (int p = lo + warp * 4; p < hi; p += nw * 4) {
        int v[4]; bool m[4];
#pragma unroll
        for (int q = 0; q < 4; q++) {
            int idx = p + q; m[q] = idx < hi;
            if (!m[q]) idx = hi - 1;
            v[q] = g_nsorted[idx];
        }
        *(float4*)&mw[0 * 128 + c] = *(const float4*)&g_msg[v[0] * H + c];
        *(float4*)&mw[1 * 128 + c] = *(const float4*)&g_msg[v[1] * H + c];
        *(float4*)&mw[2 * 128 + c] = *(const float4*)&g_msg[v[2] * H + c];
        *(float4*)&mw[3 * 128 + c] = *(const float4*)&g_msg[v[3] * H + c];
        __syncwarp();
        float4 aR0 = cR, aR1 = cR, aR2 = cR, aR3 = cR;
        float4 aZ0 = cZ, aZ1 = cZ, aZ2 = cZ, aZ3 = cZ;
        float4 aN0 = bN, aN1 = bN, aN2 = bN, aN3 = bN;
#pragma unroll 2
        for (int k = 0; k < 128; k++) {
            float m0 = mw[0 * 128 + k], m1v = mw[1 * 128 + k];
            float m2 = mw[2 * 128 + k], m3 = mw[3 * 128 + k];
            float4 wr = *(const float4*)&sWT[k * 384 + c];
            float4 wz = *(const float4*)&sWT[k * 384 + 128 + c];
            float4 wn = *(const float4*)&sWT[k * 384 + 256 + c];
            fma4(aR0, m0, wr); fma4(aZ0, m0, wz); fma4(aN0, m0, wn);
            fma4(aR1, m1v, wr); fma4(aZ1, m1v, wz); fma4(aN1, m1v, wn);
            fma4(aR2, m2, wr); fma4(aZ2, m2, wz); fma4(aN2, m2, wn);
            fma4(aR3, m3, wr); fma4(aZ3, m3, wz); fma4(aN3, m3, wn);
        }
#pragma unroll
        for (int q = 0; q < 4; q++) {
            if (!m[q]) break;
            float4 aR = (q == 0) ? aR0 : (q == 1) ? aR1 : (q == 2) ? aR2 : aR3;
            float4 aZ = (q == 0) ? aZ0 : (q == 1) ? aZ1 : (q == 2) ? aZ2 : aZ3;
            float4 aN = (q == 0) ? aN0 : (q == 1) ? aN1 : (q == 2) ? aN2 : aN3;
            float4 o;
            float r, z;
            r = sigm(aR.x); z = sigm(aZ.x); o.x = (1.f - z) * tanhf(aN.x + r * hN.x);
            r = sigm(aR.y); z = sigm(aZ.y); o.y = (1.f - z) * tanhf(aN.y + r * hN.y);
            r = sigm(aR.z); z = sigm(aZ.z); o.z = (1.f - z) * tanhf(aN.z + r * hN.z);
            r = sigm(aR.w); z = sigm(aZ.w); o.w = (1.f - z) * tanhf(aN.w + r * hN.w);
            *(float4*)&hf[v[q] * H + c] = o;
        }
        __syncwarp();
    }
}

// ---------------- launch ----------------
extern "C" void kernel_launch(void* const* d_in, const int* in_sizes, int n_in,
                              void* d_out, int out_size) {
    const int*   gate = (const int*)d_in[0];
    const int*   lvl  = (const int*)d_in[1];
    const int*   ei   = (const int*)d_in[2];
    const float* Ws   = (const float*)d_in[3];
    const float* Wt   = (const float*)d_in[4];
    const float* hsW  = (const float*)d_in[5];
    const float* hsb  = (const float*)d_in[6];
    const float* w1   = (const float*)d_in[7];
    const float* b1   = (const float*)d_in[8];
    const float* w2   = (const float*)d_in[9];
    const float* b2   = (const float*)d_in[10];
    const float* w3   = (const float*)d_in[11];
    const float* b3   = (const float*)d_in[12];
    const float* wih  = (const float*)d_in[13];
    // d_in[14] = gru_whh: provably unused (h_old == 0 for every updated node)
    const float* bih  = (const float*)d_in[15];
    const float* bhh  = (const float*)d_in[16];

    int n = in_sizes[0];
    int e = in_sizes[2] / 2;

    float* hs = (float*)d_out;            // output: [hs (N*H) | hf (N*H)]
    float* hf = hs + (size_t)n * H;

    // idempotent, called every launch (no static guards per harness rules)
    cudaFuncSetAttribute(k_level, cudaFuncAttributeMaxDynamicSharedMemorySize,
                         LVL_SMEM_FLOATS * 4);
    cudaFuncSetAttribute(k_gru, cudaFuncAttributeMaxDynamicSharedMemorySize,
                         GRU_SMEM_FLOATS * 4);

    k_comb<<<6, H>>>(Ws, Wt, hsW, hsb);
    k_table<<<dim3(6, 3), H>>>(w1, b1);
    k_transpose<<<(3 * 384 * H + 255) / 256, 256>>>(wih);
    k_init<<<(n * 32 + 255) / 256, 256>>>(gate, hs, hf, n);
    k_zero<<<1, 32>>>();
    k_count<<<(e + 255) / 256, 256>>>(ei, gate, lvl, e, n);
    k_scan<<<1, 1>>>();
    k_scatter<<<(e + 255) / 256, 256>>>(ei, gate, lvl, e, n);

    for (int lv = 1; lv < 8; lv++) {
        int b0 = (lv - 1) * 3;
        k_level<<<dim3(49, 3), 256, LVL_SMEM_FLOATS * 4>>>(
            ei, gate, w1, w2, b2, w3, b3, hf, b0, e);
        k_gru<<<dim3(49, 3), 256, GRU_SMEM_FLOATS * 4>>>(bih, bhh, hf, b0);
    }
}